// round 16
// baseline (speedup 1.0000x reference)
#include <cuda_runtime.h>
#include <cuda_fp16.h>
#include <math.h>
#include <stdint.h>

// Problem constants
#define BB   1024
#define DM   512
#define NH   8
#define HD   64
#define NN   81
#define OC   1536

// Phase-1 GEMM staging (3-stage cp.async pipeline)
#define KT     32
#define NTILES (DM / KT)     // 16
#define NSTG   3
#define RSTRIDE 80           // 64B data + 16B pad
#define WROWS  192
#define XROWS  96
#define WTILE  (WROWS * RSTRIDE)        // 15360
#define XTILE  (XROWS * RSTRIDE)        // 7680
#define STG_BYTES (WTILE + XTILE)       // 23040
#define STAGES    (NSTG * STG_BYTES)    // 69120

// fp16 planes
#define QKSTRIDE 144         // Q/K: 96 rows x (128B data + 16 pad)
#define VSTRIDE  208         // V: 64 rows, P: 96 rows x (192B data + 16 pad)
#define QKPLANE  (96 * QKSTRIDE)        // 13824
#define VPLANE   (64 * VSTRIDE)         // 13312

#define SP       84          // S row stride (floats)

// smem map: VH/VL/S overlay the (dead-by-then) stage region
#define R0_VH   0
#define R0_VL   VPLANE
#define R0_S    (2 * VPLANE)                 // 26624..54176 < STAGES
#define R0_SIZE STAGES                       // 69120
#define OFF_QH  (R0_SIZE)                    // Q hi only
#define OFF_KH  (R0_SIZE + QKPLANE)
#define OFF_KL  (R0_SIZE + 2 * QKPLANE)
#define OFF_PH  (R0_SIZE)                    // P overlays Q (+dead K-hi) after scores
#define SMEM_FUSED (R0_SIZE + 3 * QKPLANE)   // 110592 -> 2 CTAs/SM

// Scratch (fp16 inputs only)
__device__ __half g_wh[(size_t)OC * DM];
__device__ __half g_xh[(size_t)BB * 96 * DM];

__device__ __forceinline__ uint32_t smem_u32(const void* p) {
    uint32_t a;
    asm("{ .reg .u64 t; cvta.to.shared.u64 t, %1; cvt.u32.u64 %0, t; }" : "=r"(a) : "l"(p));
    return a;
}

#define CP16(dst, src) \
    asm volatile("cp.async.cg.shared.global [%0], [%1], 16;" :: "r"(dst), "l"(src))
#define CP_COMMIT() asm volatile("cp.async.commit_group;" ::: "memory")
#define CP_WAIT(n)  asm volatile("cp.async.wait_group %0;" :: "n"(n) : "memory")

#define LDSM4(r0, r1, r2, r3, addr)                                           \
    asm volatile("ldmatrix.sync.aligned.m8n8.x4.shared.b16 {%0,%1,%2,%3}, [%4];" \
        : "=r"(r0), "=r"(r1), "=r"(r2), "=r"(r3) : "r"(addr))

#define LDSM2(r0, r1, addr)                                                   \
    asm volatile("ldmatrix.sync.aligned.m8n8.x2.shared.b16 {%0,%1}, [%2];"    \
        : "=r"(r0), "=r"(r1) : "r"(addr))

#define MMA_F16(C, A, B)                                                      \
    asm volatile(                                                             \
        "mma.sync.aligned.m16n8k16.row.col.f32.f16.f16.f32 "                  \
        "{%0,%1,%2,%3}, {%4,%5,%6,%7}, {%8,%9}, {%0,%1,%2,%3};\n"             \
        : "+f"((C)[0]), "+f"((C)[1]), "+f"((C)[2]), "+f"((C)[3])              \
        : "r"((A)[0]), "r"((A)[1]), "r"((A)[2]), "r"((A)[3]),                 \
          "r"((B)[0]), "r"((B)[1]))

// split v into fp16 hi + lo, store half2-packed pair to hi/lo planes
__device__ __forceinline__ void split_store(char* smem, int offH, int offL,
                                            int byteoff, float v0, float v1) {
    __half h0 = __float2half_rn(v0);
    __half h1 = __float2half_rn(v1);
    float  l0 = v0 - __half2float(h0);
    float  l1 = v1 - __half2float(h1);
    *(__half2*)(smem + offH + byteoff) = __halves2half2(h0, h1);
    *(__half2*)(smem + offL + byteoff) =
        __halves2half2(__float2half_rn(l0), __float2half_rn(l1));
}

// ---------------------------------------------------------------------------
__global__ void prep_w(const float* __restrict__ w) {
    int i = blockIdx.x * 256 + threadIdx.x;
    g_wh[i] = __float2half_rn(w[i]);
}

__global__ __launch_bounds__(256) void prep_x(const float* __restrict__ x) {
    __shared__ float ts[64][83];
    const int b  = blockIdx.x;
    const int c0 = blockIdx.y * 64;
    const int tid = threadIdx.x;

    const float* xb = x + ((size_t)b * DM + c0) * NN;
    for (int idx = tid; idx < 64 * NN; idx += 256) {
        int c = idx / NN;
        int n = idx - c * NN;
        ts[c][n] = xb[(size_t)c * NN + n];
    }
    __syncthreads();

    for (int idx = tid; idx < 96 * 64; idx += 256) {
        int n = idx >> 6;
        int c = idx & 63;
        float v = (n < NN) ? ts[c][n] : 0.0f;
        g_xh[((size_t)b * 96 + n) * DM + c0 + c] = __float2half_rn(v);
    }
}

// ---------------------------------------------------------------------------
// Stage loader: W rows (Q|K|V for head h) + X rows for batch b
// ---------------------------------------------------------------------------
__device__ __forceinline__ void load_stage(uint32_t sb, int stage,
                                           int k0, int h64, int b, int tid) {
    const uint32_t base = sb + stage * STG_BYTES;
#pragma unroll
    for (int i = 0; i < 3; i++) {                // W: 768 chunks
        int idx = tid + i * 256;
        int row = idx >> 2;
        int chv = idx & 3;
        int o   = (row >> 6) * DM + h64 + (row & 63);
        const __half* src = g_wh + (size_t)o * DM + k0 + chv * 8;
        CP16(base + row * RSTRIDE + chv * 16, src);
    }
#pragma unroll
    for (int i = 0; i < 2; i++) {                // X: 384 chunks
        int idx = tid + i * 256;
        if (idx < 384) {
            int row = idx >> 2;
            int chv = idx & 3;
            const __half* src = g_xh + ((size_t)b * 96 + row) * DM + k0 + chv * 8;
            CP16(base + WTILE + row * RSTRIDE + chv * 16, src);
        }
    }
    CP_COMMIT();
}

// ---------------------------------------------------------------------------
// Fused kernel: QKV GEMM + scores (2-term) + softmax + PV (2-term), fp16 HMMA
// Dead-token MMAs trimmed (reads never trimmed — every smem byte read is
// written first; the R15 NaN came from reading never-written pad garbage).
// 3-stage pipeline, 1 barrier/chunk.
// ---------------------------------------------------------------------------
__global__ __launch_bounds__(256, 2) void fused_mhsa(const float* __restrict__ bias,
                                                     const float* __restrict__ rel_h,
                                                     const float* __restrict__ rel_w,
                                                     float* __restrict__ out) {
    extern __shared__ char smem[];
    const uint32_t sb = smem_u32(smem);
    float* Sf = (float*)(smem + R0_S);

    const int tid  = threadIdx.x;
    const int bh   = blockIdx.x;
    const int b    = bh >> 3;
    const int h64  = (bh & 7) * HD;
    const int warp = tid >> 5;
    const int lane = tid & 31;
    const int g    = lane >> 2;
    const int l4   = lane & 3;

    const uint32_t arow = (lane & 7) + ((lane >> 3) & 1) * 8;
    const uint32_t acol = (lane >> 4) * 16;
    const uint32_t brow = (lane & 7) + ((lane >> 4) & 1) * 8;
    const uint32_t bcol = ((lane >> 3) & 1) * 16;
    const uint32_t aoff80  = arow * 80  + acol;
    const uint32_t boff80  = brow * 80  + bcol;
    const uint32_t aoff144 = arow * 144 + acol;
    const uint32_t boff144 = brow * 144 + bcol;
    const uint32_t aoff208 = arow * 208 + acol;
    const uint32_t boff208 = brow * 208 + bcol;
    const uint32_t b2off   = (lane & 7);             // LDSM2 row part
    const uint32_t b2col   = ((lane >> 3) & 1) * 16; // LDSM2 col part

    // ================= Phase 1: QKV projection =================
    const int wA = warp & 1;    // M half
    const int wB = warp >> 1;   // N quarter (0..3)

    float qk[3][4][4];
    float vv[2][3][4];
#pragma unroll
    for (int i = 0; i < 3; i++)
#pragma unroll
        for (int j = 0; j < 4; j++)
#pragma unroll
            for (int r = 0; r < 4; r++) qk[i][j][r] = 0.0f;
#pragma unroll
    for (int i = 0; i < 2; i++)
#pragma unroll
        for (int j = 0; j < 3; j++)
#pragma unroll
            for (int r = 0; r < 4; r++) vv[i][j][r] = 0.0f;

    load_stage(sb, 0, 0, h64, b, tid);
    load_stage(sb, 1, KT, h64, b, tid);

    for (int ch = 0; ch < NTILES; ch++) {
        if (ch + 1 < NTILES) { CP_WAIT(1); } else { CP_WAIT(0); }
        __syncthreads();
        // refill the buffer read two iterations ago (all warps past that read)
        if (ch + 2 < NTILES)
            load_stage(sb, (ch + 2) % NSTG, (ch + 2) * KT, h64, b, tid);

        const uint32_t Wt = sb + (ch % NSTG) * STG_BYTES;
        const uint32_t Xt = Wt + WTILE;

#pragma unroll
        for (int ks = 0; ks < 2; ks++) {
            const uint32_t kb = ks * 32;
            // --- QK ---
            uint32_t a[3][4];
#pragma unroll
            for (int mi = 0; mi < 3; mi++)
                LDSM4(a[mi][0], a[mi][1], a[mi][2], a[mi][3],
                      Xt + (uint32_t)((wA * 48 + mi * 16) * 80) + kb + aoff80);
            uint32_t bw[2][4];
#pragma unroll
            for (int pr = 0; pr < 2; pr++)
                LDSM4(bw[pr][0], bw[pr][1], bw[pr][2], bw[pr][3],
                      Wt + (uint32_t)((wB * 32 + pr * 16) * 80) + kb + boff80);
#pragma unroll
            for (int pr = 0; pr < 2; pr++)
#pragma unroll
                for (int sub = 0; sub < 2; sub++)
#pragma unroll
                    for (int mi = 0; mi < 3; mi++)
                        MMA_F16(qk[mi][pr * 2 + sub], a[mi], bw[pr] + 2 * sub);
            // --- V ---
            uint32_t av[2][4];
#pragma unroll
            for (int mi = 0; mi < 2; mi++)
                LDSM4(av[mi][0], av[mi][1], av[mi][2], av[mi][3],
                      Wt + (uint32_t)((128 + wA * 32 + mi * 16) * 80) + kb + aoff80);
            uint32_t bx0[4], bx2[2];
            LDSM4(bx0[0], bx0[1], bx0[2], bx0[3],
                  Xt + (uint32_t)((wB * 24) * 80) + kb + boff80);
#pragma unroll
            for (int mi = 0; mi < 2; mi++) {
                MMA_F16(vv[mi][0], av[mi], bx0 + 0);
                MMA_F16(vv[mi][1], av[mi], bx0 + 2);
            }
            if (wB < 3) {   // tokens 88-95: X is zero-padded -> vv[*][2] stays 0
                LDSM2(bx2[0], bx2[1],
                      Xt + (uint32_t)((wB * 24 + 16 + b2off) * 80) + kb + b2col);
#pragma unroll
                for (int mi = 0; mi < 2; mi++)
                    MMA_F16(vv[mi][2], av[mi], bx2);
            }
        }
    }
    __syncthreads();   // stages dead; VH/VL/S overlay them below

    // ---- Epilogue 1a: Q (hi only) / K (hi+lo) -> fp16 planes [token][d] ----
#pragma unroll
    for (int mi = 0; mi < 3; mi++) {
#pragma unroll
        for (int rr = 0; rr < 2; rr++) {
            const int tok = wA * 48 + mi * 16 + g + rr * 8;
            const int tc  = (tok < NN) ? tok : 80;
#pragma unroll
            for (int ni = 0; ni < 4; ni++) {
                const int o  = wB * 32 + ni * 8 + 2 * l4;
                float c0 = qk[mi][ni][rr * 2 + 0];
                float c1 = qk[mi][ni][rr * 2 + 1];
                if (wB < 2) {          // Q: single fp16 plane
                    c0 += bias[h64 + o];
                    c1 += bias[h64 + o + 1];
                    *(__half2*)(smem + OFF_QH + tok * QKSTRIDE + 2 * o) =
                        __halves2half2(__float2half_rn(c0), __float2half_rn(c1));
                } else {               // K (+rel fold): hi/lo split
                    const int d = o - 64;
                    c0 += bias[512 + h64 + d]
                        + rel_h[(h64 + d) * 9 + tc % 9] + rel_w[(h64 + d) * 9 + tc / 9];
                    c1 += bias[512 + h64 + d + 1]
                        + rel_h[(h64 + d + 1) * 9 + tc % 9] + rel_w[(h64 + d + 1) * 9 + tc / 9];
                    split_store(smem, OFF_KH, OFF_KL, tok * QKSTRIDE + 2 * d, c0, c1);
                }
            }
        }
    }
    // ---- Epilogue 1b: V accums -> fp16 hi/lo planes [d][token] ----
    // ALL tokens written (tokens 88-95 get vv=0 -> bias), so phase-3 never
    // reads never-written smem (0 x Inf = NaN was the R15 failure).
#pragma unroll
    for (int mi = 0; mi < 2; mi++) {
#pragma unroll
        for (int rr = 0; rr < 2; rr++) {
            const int d  = wA * 32 + mi * 16 + g + rr * 8;
            const float bv = bias[1024 + h64 + d];
#pragma unroll
            for (int ni = 0; ni < 3; ni++) {
                const int tok = wB * 24 + ni * 8 + 2 * l4;
                split_store(smem, R0_VH, R0_VL, d * VSTRIDE + 2 * tok,
                            vv[mi][ni][rr * 2] + bv, vv[mi][ni][rr * 2 + 1] + bv);
            }
        }
    }
    __syncthreads();

    // ===== Phase 2: S = Qh.(Kh+Kl)^T — warps n(2) x m(4), full k, no combine
    {
        const int sn  = warp & 1;      // n half (48 rows of Q)
        const int sm2 = warp >> 1;     // m quarter (24 rows of K)
        float sc[3][3][4];
#pragma unroll
        for (int i = 0; i < 3; i++)
#pragma unroll
            for (int j = 0; j < 3; j++)
#pragma unroll
                for (int r = 0; r < 4; r++) sc[i][j][r] = 0.0f;

#pragma unroll
        for (int ks = 0; ks < 4; ks++) {
            const uint32_t kb = ks * 32;
            uint32_t ah[3][4];
#pragma unroll
            for (int mi = 0; mi < 3; mi++)
                LDSM4(ah[mi][0], ah[mi][1], ah[mi][2], ah[mi][3],
                      sb + OFF_QH + (uint32_t)((sn * 48 + mi * 16) * QKSTRIDE) + kb + aoff144);
            uint32_t bk4[4], bk2[2];
            // K hi
            LDSM4(bk4[0], bk4[1], bk4[2], bk4[3],
                  sb + OFF_KH + (uint32_t)((sm2 * 24) * QKSTRIDE) + kb + boff144);
#pragma unroll
            for (int sub = 0; sub < 2; sub++)
#pragma unroll
                for (int mi = 0; mi < 3; mi++)
                    MMA_F16(sc[mi][sub], ah[mi], bk4 + 2 * sub);
            if (sm2 < 3) {  // m 88-95 dead (outputs guarded out of S)
                LDSM2(bk2[0], bk2[1],
                      sb + OFF_KH + (uint32_t)((sm2 * 24 + 16 + b2off) * QKSTRIDE) + kb + b2col);
#pragma unroll
                for (int mi = 0; mi < 3; mi++)
                    MMA_F16(sc[mi][2], ah[mi], bk2);
            }
            // K lo
            LDSM4(bk4[0], bk4[1], bk4[2], bk4[3],
                  sb + OFF_KL + (uint32_t)((sm2 * 24) * QKSTRIDE) + kb + boff144);
#pragma unroll
            for (int sub = 0; sub < 2; sub++)
#pragma unroll
                for (int mi = 0; mi < 3; mi++)
                    MMA_F16(sc[mi][sub], ah[mi], bk4 + 2 * sub);
            if (sm2 < 3) {
                LDSM2(bk2[0], bk2[1],
                      sb + OFF_KL + (uint32_t)((sm2 * 24 + 16 + b2off) * QKSTRIDE) + kb + b2col);
#pragma unroll
                for (int mi = 0; mi < 3; mi++)
                    MMA_F16(sc[mi][2], ah[mi], bk2);
            }
        }
        // direct unique write to S
#pragma unroll
        for (int mi = 0; mi < 3; mi++)
#pragma unroll
            for (int nt = 0; nt < 3; nt++)
#pragma unroll
                for (int rr = 0; rr < 2; rr++) {
                    const int n = sn * 48 + mi * 16 + g + rr * 8;
                    const int m = sm2 * 24 + nt * 8 + 2 * l4;
                    if (n < 82 && m < 82)
                        *(float2*)(Sf + n * SP + m) =
                            make_float2(sc[mi][nt][rr * 2], sc[mi][nt][rr * 2 + 1]);
                }
    }
    __syncthreads();

    // ---- softmax (warp per row) fused with Ph fp16 write + zero-pad cols ----
    for (int r = warp; r < NN; r += 8) {
        float* row = Sf + r * SP;
        float mx = -1e30f;
        for (int m = lane; m < NN; m += 32) mx = fmaxf(mx, row[m]);
#pragma unroll
        for (int s = 16; s > 0; s >>= 1)
            mx = fmaxf(mx, __shfl_xor_sync(0xFFFFFFFF, mx, s));
        float sum = 0.0f;
        for (int m = lane; m < NN; m += 32) {
            float e = __expf(row[m] - mx);
            row[m] = e;
            sum += e;
        }
#pragma unroll
        for (int s = 16; s > 0; s >>= 1)
            sum += __shfl_xor_sync(0xFFFFFFFF, sum, s);
        float inv = 1.0f / sum;
        for (int m = lane; m < 96; m += 32) {
            float v = (m < NN) ? row[m] * inv : 0.0f;
            *(__half*)(smem + OFF_PH + r * VSTRIDE + 2 * m) = __float2half_rn(v);
        }
    }
    __syncthreads();

    // ===== Phase 3: O = Ph.(Vh+Vl) — warps n(2) x d(4), full k, direct gmem
    {
        const int pn  = warp & 1;      // n half (48)
        const int pd2 = warp >> 1;     // d quarter (16)
        float ov[3][2][4];
#pragma unroll
        for (int i = 0; i < 3; i++)
#pragma unroll
            for (int j = 0; j < 2; j++)
#pragma unroll
                for (int r = 0; r < 4; r++) ov[i][j][r] = 0.0f;

#pragma unroll
        for (int ks = 0; ks < 6; ks++) {
            const uint32_t kb = ks * 32;
            uint32_t a[3][4];
#pragma unroll
            for (int mi = 0; mi < 3; mi++)
                LDSM4(a[mi][0], a[mi][1], a[mi][2], a[mi][3],
                      sb + OFF_PH + (uint32_t)((pn * 48 + mi * 16) * VSTRIDE) + kb + aoff208);
            uint32_t bv4[4];
            LDSM4(bv4[0], bv4[1], bv4[2], bv4[3],
                  sb + R0_VH + (uint32_t)((pd2 * 16) * VSTRIDE) + kb + boff208);
#pragma unroll
            for (int sub = 0; sub < 2; sub++)
#pragma unroll
                for (int mi = 0; mi < 3; mi++)
                    MMA_F16(ov[mi][sub], a[mi], bv4 + 2 * sub);   // Ph*Vh
            LDSM4(bv4[0], bv4[1], bv4[2], bv4[3],
                  sb + R0_VL + (uint32_t)((pd2 * 16) * VSTRIDE) + kb + boff208);
#pragma unroll
            for (int sub = 0; sub < 2; sub++)
#pragma unroll
                for (int mi = 0; mi < 3; mi++)
                    MMA_F16(ov[mi][sub], a[mi], bv4 + 2 * sub);   // Ph*Vl
        }
        // direct unique write to gmem
#pragma unroll
        for (int mi = 0; mi < 3; mi++)
#pragma unroll
            for (int sub = 0; sub < 2; sub++)
#pragma unroll
                for (int rr = 0; rr < 2; rr++) {
                    const int n = pn * 48 + mi * 16 + g + rr * 8;
                    const int d = pd2 * 16 + sub * 8 + 2 * l4;
                    if (n < NN) {
                        float* dst = out + ((size_t)b * DM + h64 + d) * NN + n;
                        dst[0]  = ov[mi][sub][rr * 2];
                        dst[NN] = ov[mi][sub][rr * 2 + 1];
                    }
                }
    }
}

// ---------------------------------------------------------------------------
extern "C" void kernel_launch(void* const* d_in, const int* in_sizes, int n_in,
                              void* d_out, int out_size) {
    const float* x     = (const float*)d_in[0];
    const float* qkv_w = (const float*)d_in[1];
    const float* qkv_b = (const float*)d_in[2];
    const float* rel_h = (const float*)d_in[3];
    const float* rel_w = (const float*)d_in[4];
    float* out = (float*)d_out;

    cudaFuncSetAttribute(fused_mhsa, cudaFuncAttributeMaxDynamicSharedMemorySize, SMEM_FUSED);

    prep_w<<<OC * DM / 256, 256>>>(qkv_w);
    prep_x<<<dim3(BB, DM / 64), 256>>>(x);
    fused_mhsa<<<BB * NH, 256, SMEM_FUSED>>>(qkv_b, rel_h, rel_w, out);
}

// round 17
// speedup vs baseline: 1.0019x; 1.0019x over previous
#include <cuda_runtime.h>
#include <cuda_fp16.h>
#include <math.h>
#include <stdint.h>

// Problem constants
#define BB   1024
#define DM   512
#define NH   8
#define HD   64
#define NN   81
#define OC   1536

// Phase-1 GEMM staging (2-stage cp.async pipeline)
#define KT     32
#define NTILES (DM / KT)     // 16
#define RSTRIDE 80           // 64B data + 16B pad
#define WROWS  192
#define XROWS  96
#define WTILE  (WROWS * RSTRIDE)        // 15360
#define XTILE  (XROWS * RSTRIDE)        // 7680
#define STG_BYTES (WTILE + XTILE)       // 23040
#define STAGES    (2 * STG_BYTES)       // 46080

// fp16 planes
#define QKSTRIDE 144         // Q/K: 96 rows x (128B data + 16 pad)
#define VSTRIDE  208         // V: 64 rows, P: 96 rows x (192B data + 16 pad)
#define QKPLANE  (96 * QKSTRIDE)        // 13824
#define VPLANE   (64 * VSTRIDE)         // 13312

#define SP       84          // S row stride (floats)

// smem map (R14): VH/VL/S overlay the dead stage region; 95648 B total
#define R0_VH   0
#define R0_VL   VPLANE
#define R0_S    (2 * VPLANE)                 // 26624
#define R0_SIZE (R0_S + 82 * SP * 4)         // 54176
#define OFF_QH  (R0_SIZE)                    // Q hi only
#define OFF_KH  (R0_SIZE + QKPLANE)
#define OFF_KL  (R0_SIZE + 2 * QKPLANE)
#define OFF_PH  (R0_SIZE)                    // P overlays Q (+dead K-hi) after scores
#define SMEM_FUSED (R0_SIZE + 3 * QKPLANE)   // 95648 -> 2 CTAs/SM, L1D ~37KB

// Scratch (fp16 inputs only)
__device__ __half g_wh[(size_t)OC * DM];
__device__ __half g_xh[(size_t)BB * 96 * DM];

__device__ __forceinline__ uint32_t smem_u32(const void* p) {
    uint32_t a;
    asm("{ .reg .u64 t; cvta.to.shared.u64 t, %1; cvt.u32.u64 %0, t; }" : "=r"(a) : "l"(p));
    return a;
}

#define CP16(dst, src) \
    asm volatile("cp.async.cg.shared.global [%0], [%1], 16;" :: "r"(dst), "l"(src))
#define CP_COMMIT() asm volatile("cp.async.commit_group;" ::: "memory")
#define CP_WAIT(n)  asm volatile("cp.async.wait_group %0;" :: "n"(n) : "memory")

#define LDSM4(r0, r1, r2, r3, addr)                                           \
    asm volatile("ldmatrix.sync.aligned.m8n8.x4.shared.b16 {%0,%1,%2,%3}, [%4];" \
        : "=r"(r0), "=r"(r1), "=r"(r2), "=r"(r3) : "r"(addr))

#define LDSM2(r0, r1, addr)                                                   \
    asm volatile("ldmatrix.sync.aligned.m8n8.x2.shared.b16 {%0,%1}, [%2];"    \
        : "=r"(r0), "=r"(r1) : "r"(addr))

#define MMA_F16(C, A, B)                                                      \
    asm volatile(                                                             \
        "mma.sync.aligned.m16n8k16.row.col.f32.f16.f16.f32 "                  \
        "{%0,%1,%2,%3}, {%4,%5,%6,%7}, {%8,%9}, {%0,%1,%2,%3};\n"             \
        : "+f"((C)[0]), "+f"((C)[1]), "+f"((C)[2]), "+f"((C)[3])              \
        : "r"((A)[0]), "r"((A)[1]), "r"((A)[2]), "r"((A)[3]),                 \
          "r"((B)[0]), "r"((B)[1]))

// split v into fp16 hi + lo, store half2-packed pair to hi/lo planes
__device__ __forceinline__ void split_store(char* smem, int offH, int offL,
                                            int byteoff, float v0, float v1) {
    __half h0 = __float2half_rn(v0);
    __half h1 = __float2half_rn(v1);
    float  l0 = v0 - __half2float(h0);
    float  l1 = v1 - __half2float(h1);
    *(__half2*)(smem + offH + byteoff) = __halves2half2(h0, h1);
    *(__half2*)(smem + offL + byteoff) =
        __halves2half2(__float2half_rn(l0), __float2half_rn(l1));
}

// ---------------------------------------------------------------------------
// Combined prep: transpose+convert X slice AND convert a 96-element W chunk.
// Grid (1024, 8); W total = 1536*512 = 8192 blocks * 96 elems.
// ---------------------------------------------------------------------------
__global__ __launch_bounds__(256) void prep_xw(const float* __restrict__ x,
                                               const float* __restrict__ w) {
    __shared__ float ts[64][83];
    const int b  = blockIdx.x;
    const int c0 = blockIdx.y * 64;
    const int tid = threadIdx.x;

    // W chunk (96 elems per block), overlapped with the X smem fill
    if (tid < 96) {
        int i = (b * 8 + blockIdx.y) * 96 + tid;
        g_wh[i] = __float2half_rn(w[i]);
    }

    const float* xb = x + ((size_t)b * DM + c0) * NN;
    for (int idx = tid; idx < 64 * NN; idx += 256) {
        int c = idx / NN;
        int n = idx - c * NN;
        ts[c][n] = xb[(size_t)c * NN + n];
    }
    __syncthreads();

    for (int idx = tid; idx < 96 * 64; idx += 256) {
        int n = idx >> 6;
        int c = idx & 63;
        float v = (n < NN) ? ts[c][n] : 0.0f;
        g_xh[((size_t)b * 96 + n) * DM + c0 + c] = __float2half_rn(v);
    }
}

// ---------------------------------------------------------------------------
// Stage loader: W rows (Q|K|V for head h) + X rows for batch b
// ---------------------------------------------------------------------------
__device__ __forceinline__ void load_stage(uint32_t sb, int stage,
                                           int k0, int h64, int b, int tid) {
    const uint32_t base = sb + stage * STG_BYTES;
#pragma unroll
    for (int i = 0; i < 3; i++) {                // W: 768 chunks
        int idx = tid + i * 256;
        int row = idx >> 2;
        int chv = idx & 3;
        int o   = (row >> 6) * DM + h64 + (row & 63);
        const __half* src = g_wh + (size_t)o * DM + k0 + chv * 8;
        CP16(base + row * RSTRIDE + chv * 16, src);
    }
#pragma unroll
    for (int i = 0; i < 2; i++) {                // X: 384 chunks
        int idx = tid + i * 256;
        if (idx < 384) {
            int row = idx >> 2;
            int chv = idx & 3;
            const __half* src = g_xh + ((size_t)b * 96 + row) * DM + k0 + chv * 8;
            CP16(base + WTILE + row * RSTRIDE + chv * 16, src);
        }
    }
    CP_COMMIT();
}

// ---------------------------------------------------------------------------
// Fused kernel: QKV GEMM + scores (2-term) + softmax + PV (2-term), fp16 HMMA
// R14 pipeline/smem map + dead-token MMA trims (reads never trimmed).
// ---------------------------------------------------------------------------
__global__ __launch_bounds__(256, 2) void fused_mhsa(const float* __restrict__ bias,
                                                     const float* __restrict__ rel_h,
                                                     const float* __restrict__ rel_w,
                                                     float* __restrict__ out) {
    extern __shared__ char smem[];
    const uint32_t sb = smem_u32(smem);
    float* Sf = (float*)(smem + R0_S);

    const int tid  = threadIdx.x;
    const int bh   = blockIdx.x;
    const int b    = bh >> 3;
    const int h64  = (bh & 7) * HD;
    const int warp = tid >> 5;
    const int lane = tid & 31;
    const int g    = lane >> 2;
    const int l4   = lane & 3;

    const uint32_t arow = (lane & 7) + ((lane >> 3) & 1) * 8;
    const uint32_t acol = (lane >> 4) * 16;
    const uint32_t brow = (lane & 7) + ((lane >> 4) & 1) * 8;
    const uint32_t bcol = ((lane >> 3) & 1) * 16;
    const uint32_t aoff80  = arow * 80  + acol;
    const uint32_t boff80  = brow * 80  + bcol;
    const uint32_t aoff144 = arow * 144 + acol;
    const uint32_t boff144 = brow * 144 + bcol;
    const uint32_t aoff208 = arow * 208 + acol;
    const uint32_t boff208 = brow * 208 + bcol;
    const uint32_t b2off   = (lane & 7);             // LDSM2 row part
    const uint32_t b2col   = ((lane >> 3) & 1) * 16; // LDSM2 col part

    // ================= Phase 1: QKV projection =================
    const int wA = warp & 1;    // M half
    const int wB = warp >> 1;   // N quarter (0..3)

    float qk[3][4][4];
    float vv[2][3][4];
#pragma unroll
    for (int i = 0; i < 3; i++)
#pragma unroll
        for (int j = 0; j < 4; j++)
#pragma unroll
            for (int r = 0; r < 4; r++) qk[i][j][r] = 0.0f;
#pragma unroll
    for (int i = 0; i < 2; i++)
#pragma unroll
        for (int j = 0; j < 3; j++)
#pragma unroll
            for (int r = 0; r < 4; r++) vv[i][j][r] = 0.0f;

    load_stage(sb, 0, 0, h64, b, tid);
    load_stage(sb, 1, KT, h64, b, tid);

    for (int ch = 0; ch < NTILES; ch++) {
        if (ch + 1 < NTILES) { CP_WAIT(1); } else { CP_WAIT(0); }
        __syncthreads();

        const uint32_t Wt = sb + (ch & 1) * STG_BYTES;
        const uint32_t Xt = Wt + WTILE;

#pragma unroll
        for (int ks = 0; ks < 2; ks++) {
            const uint32_t kb = ks * 32;
            // --- QK ---
            uint32_t a[3][4];
#pragma unroll
            for (int mi = 0; mi < 3; mi++)
                LDSM4(a[mi][0], a[mi][1], a[mi][2], a[mi][3],
                      Xt + (uint32_t)((wA * 48 + mi * 16) * 80) + kb + aoff80);
            uint32_t bw[2][4];
#pragma unroll
            for (int pr = 0; pr < 2; pr++)
                LDSM4(bw[pr][0], bw[pr][1], bw[pr][2], bw[pr][3],
                      Wt + (uint32_t)((wB * 32 + pr * 16) * 80) + kb + boff80);
#pragma unroll
            for (int pr = 0; pr < 2; pr++)
#pragma unroll
                for (int sub = 0; sub < 2; sub++)
#pragma unroll
                    for (int mi = 0; mi < 3; mi++)
                        MMA_F16(qk[mi][pr * 2 + sub], a[mi], bw[pr] + 2 * sub);
            // --- V ---
            uint32_t av[2][4];
#pragma unroll
            for (int mi = 0; mi < 2; mi++)
                LDSM4(av[mi][0], av[mi][1], av[mi][2], av[mi][3],
                      Wt + (uint32_t)((128 + wA * 32 + mi * 16) * 80) + kb + aoff80);
            uint32_t bx0[4], bx2[2];
            LDSM4(bx0[0], bx0[1], bx0[2], bx0[3],
                  Xt + (uint32_t)((wB * 24) * 80) + kb + boff80);
#pragma unroll
            for (int mi = 0; mi < 2; mi++) {
                MMA_F16(vv[mi][0], av[mi], bx0 + 0);
                MMA_F16(vv[mi][1], av[mi], bx0 + 2);
            }
            if (wB < 3) {   // tokens 88-95: X zero-padded, vv[*][2] stays 0
                LDSM2(bx2[0], bx2[1],
                      Xt + (uint32_t)((wB * 24 + 16 + b2off) * 80) + kb + b2col);
#pragma unroll
                for (int mi = 0; mi < 2; mi++)
                    MMA_F16(vv[mi][2], av[mi], bx2);
            }
        }

        if (ch + 2 < NTILES) {
            __syncthreads();   // all warps done reading buffer (ch&1) before refill
            load_stage(sb, ch & 1, (ch + 2) * KT, h64, b, tid);
        }
    }
    __syncthreads();   // stages dead; VH/VL/S overlay them below

    // ---- Epilogue 1a: Q (hi only) / K (hi+lo) -> fp16 planes [token][d] ----
#pragma unroll
    for (int mi = 0; mi < 3; mi++) {
#pragma unroll
        for (int rr = 0; rr < 2; rr++) {
            const int tok = wA * 48 + mi * 16 + g + rr * 8;
            const int tc  = (tok < NN) ? tok : 80;
#pragma unroll
            for (int ni = 0; ni < 4; ni++) {
                const int o  = wB * 32 + ni * 8 + 2 * l4;
                float c0 = qk[mi][ni][rr * 2 + 0];
                float c1 = qk[mi][ni][rr * 2 + 1];
                if (wB < 2) {          // Q: single fp16 plane
                    c0 += bias[h64 + o];
                    c1 += bias[h64 + o + 1];
                    *(__half2*)(smem + OFF_QH + tok * QKSTRIDE + 2 * o) =
                        __halves2half2(__float2half_rn(c0), __float2half_rn(c1));
                } else {               // K (+rel fold): hi/lo split
                    const int d = o - 64;
                    c0 += bias[512 + h64 + d]
                        + rel_h[(h64 + d) * 9 + tc % 9] + rel_w[(h64 + d) * 9 + tc / 9];
                    c1 += bias[512 + h64 + d + 1]
                        + rel_h[(h64 + d + 1) * 9 + tc % 9] + rel_w[(h64 + d + 1) * 9 + tc / 9];
                    split_store(smem, OFF_KH, OFF_KL, tok * QKSTRIDE + 2 * d, c0, c1);
                }
            }
        }
    }
    // ---- Epilogue 1b: V accums -> fp16 hi/lo planes [d][token] ----
    // ALL tokens written (dead 88-95 get vv=0 -> bias): phase-3 reads are safe.
#pragma unroll
    for (int mi = 0; mi < 2; mi++) {
#pragma unroll
        for (int rr = 0; rr < 2; rr++) {
            const int d  = wA * 32 + mi * 16 + g + rr * 8;
            const float bv = bias[1024 + h64 + d];
#pragma unroll
            for (int ni = 0; ni < 3; ni++) {
                const int tok = wB * 24 + ni * 8 + 2 * l4;
                split_store(smem, R0_VH, R0_VL, d * VSTRIDE + 2 * tok,
                            vv[mi][ni][rr * 2] + bv, vv[mi][ni][rr * 2 + 1] + bv);
            }
        }
    }
    __syncthreads();

    // ===== Phase 2: S = Qh.(Kh+Kl)^T — warps n(2) x m(4), full k, no combine
    {
        const int sn  = warp & 1;      // n half (48 rows of Q)
        const int sm2 = warp >> 1;     // m quarter (24 rows of K)
        float sc[3][3][4];
#pragma unroll
        for (int i = 0; i < 3; i++)
#pragma unroll
            for (int j = 0; j < 3; j++)
#pragma unroll
                for (int r = 0; r < 4; r++) sc[i][j][r] = 0.0f;

#pragma unroll
        for (int ks = 0; ks < 4; ks++) {
            const uint32_t kb = ks * 32;
            uint32_t ah[3][4];
#pragma unroll
            for (int mi = 0; mi < 3; mi++)
                LDSM4(ah[mi][0], ah[mi][1], ah[mi][2], ah[mi][3],
                      sb + OFF_QH + (uint32_t)((sn * 48 + mi * 16) * QKSTRIDE) + kb + aoff144);
            uint32_t bk4[4], bk2[2];
            // K hi
            LDSM4(bk4[0], bk4[1], bk4[2], bk4[3],
                  sb + OFF_KH + (uint32_t)((sm2 * 24) * QKSTRIDE) + kb + boff144);
#pragma unroll
            for (int sub = 0; sub < 2; sub++)
#pragma unroll
                for (int mi = 0; mi < 3; mi++)
                    MMA_F16(sc[mi][sub], ah[mi], bk4 + 2 * sub);
            if (sm2 < 3) {  // m 88-95 dead (outputs guarded out of S)
                LDSM2(bk2[0], bk2[1],
                      sb + OFF_KH + (uint32_t)((sm2 * 24 + 16 + b2off) * QKSTRIDE) + kb + b2col);
#pragma unroll
                for (int mi = 0; mi < 3; mi++)
                    MMA_F16(sc[mi][2], ah[mi], bk2);
            }
            // K lo
            LDSM4(bk4[0], bk4[1], bk4[2], bk4[3],
                  sb + OFF_KL + (uint32_t)((sm2 * 24) * QKSTRIDE) + kb + boff144);
#pragma unroll
            for (int sub = 0; sub < 2; sub++)
#pragma unroll
                for (int mi = 0; mi < 3; mi++)
                    MMA_F16(sc[mi][sub], ah[mi], bk4 + 2 * sub);
            if (sm2 < 3) {
                LDSM2(bk2[0], bk2[1],
                      sb + OFF_KL + (uint32_t)((sm2 * 24 + 16 + b2off) * QKSTRIDE) + kb + b2col);
#pragma unroll
                for (int mi = 0; mi < 3; mi++)
                    MMA_F16(sc[mi][2], ah[mi], bk2);
            }
        }
        // direct unique write to S
#pragma unroll
        for (int mi = 0; mi < 3; mi++)
#pragma unroll
            for (int nt = 0; nt < 3; nt++)
#pragma unroll
                for (int rr = 0; rr < 2; rr++) {
                    const int n = sn * 48 + mi * 16 + g + rr * 8;
                    const int m = sm2 * 24 + nt * 8 + 2 * l4;
                    if (n < 82 && m < 82)
                        *(float2*)(Sf + n * SP + m) =
                            make_float2(sc[mi][nt][rr * 2], sc[mi][nt][rr * 2 + 1]);
                }
    }
    __syncthreads();

    // ---- softmax (warp per row) fused with Ph fp16 write + zero-pad cols ----
    for (int r = warp; r < NN; r += 8) {
        float* row = Sf + r * SP;
        float mx = -1e30f;
        for (int m = lane; m < NN; m += 32) mx = fmaxf(mx, row[m]);
#pragma unroll
        for (int s = 16; s > 0; s >>= 1)
            mx = fmaxf(mx, __shfl_xor_sync(0xFFFFFFFF, mx, s));
        float sum = 0.0f;
        for (int m = lane; m < NN; m += 32) {
            float e = __expf(row[m] - mx);
            row[m] = e;
            sum += e;
        }
#pragma unroll
        for (int s = 16; s > 0; s >>= 1)
            sum += __shfl_xor_sync(0xFFFFFFFF, sum, s);
        float inv = 1.0f / sum;
        for (int m = lane; m < 96; m += 32) {
            float v = (m < NN) ? row[m] * inv : 0.0f;
            *(__half*)(smem + OFF_PH + r * VSTRIDE + 2 * m) = __float2half_rn(v);
        }
    }
    __syncthreads();

    // ===== Phase 3: O = Ph.(Vh+Vl) — warps n(2) x d(4), full k, direct gmem
    {
        const int pn  = warp & 1;      // n half (48)
        const int pd2 = warp >> 1;     // d quarter (16)
        float ov[3][2][4];
#pragma unroll
        for (int i = 0; i < 3; i++)
#pragma unroll
            for (int j = 0; j < 2; j++)
#pragma unroll
                for (int r = 0; r < 4; r++) ov[i][j][r] = 0.0f;

#pragma unroll
        for (int ks = 0; ks < 6; ks++) {
            const uint32_t kb = ks * 32;
            uint32_t a[3][4];
#pragma unroll
            for (int mi = 0; mi < 3; mi++)
                LDSM4(a[mi][0], a[mi][1], a[mi][2], a[mi][3],
                      sb + OFF_PH + (uint32_t)((pn * 48 + mi * 16) * VSTRIDE) + kb + aoff208);
            uint32_t bv4[4];
            LDSM4(bv4[0], bv4[1], bv4[2], bv4[3],
                  sb + R0_VH + (uint32_t)((pd2 * 16) * VSTRIDE) + kb + boff208);
#pragma unroll
            for (int sub = 0; sub < 2; sub++)
#pragma unroll
                for (int mi = 0; mi < 3; mi++)
                    MMA_F16(ov[mi][sub], a[mi], bv4 + 2 * sub);   // Ph*Vh
            LDSM4(bv4[0], bv4[1], bv4[2], bv4[3],
                  sb + R0_VL + (uint32_t)((pd2 * 16) * VSTRIDE) + kb + boff208);
#pragma unroll
            for (int sub = 0; sub < 2; sub++)
#pragma unroll
                for (int mi = 0; mi < 3; mi++)
                    MMA_F16(ov[mi][sub], a[mi], bv4 + 2 * sub);   // Ph*Vl
        }
        // direct unique write to gmem
#pragma unroll
        for (int mi = 0; mi < 3; mi++)
#pragma unroll
            for (int sub = 0; sub < 2; sub++)
#pragma unroll
                for (int rr = 0; rr < 2; rr++) {
                    const int n = pn * 48 + mi * 16 + g + rr * 8;
                    const int d = pd2 * 16 + sub * 8 + 2 * l4;
                    if (n < NN) {
                        float* dst = out + ((size_t)b * DM + h64 + d) * NN + n;
                        dst[0]  = ov[mi][sub][rr * 2];
                        dst[NN] = ov[mi][sub][rr * 2 + 1];
                    }
                }
    }
}

// ---------------------------------------------------------------------------
extern "C" void kernel_launch(void* const* d_in, const int* in_sizes, int n_in,
                              void* d_out, int out_size) {
    const float* x     = (const float*)d_in[0];
    const float* qkv_w = (const float*)d_in[1];
    const float* qkv_b = (const float*)d_in[2];
    const float* rel_h = (const float*)d_in[3];
    const float* rel_w = (const float*)d_in[4];
    float* out = (float*)d_out;

    cudaFuncSetAttribute(fused_mhsa, cudaFuncAttributeMaxDynamicSharedMemorySize, SMEM_FUSED);

    prep_xw<<<dim3(BB, DM / 64), 256>>>(x, qkv_w);
    fused_mhsa<<<BB * NH, 256, SMEM_FUSED>>>(qkv_b, rel_h, rel_w, out);
}